// round 14
// baseline (speedup 1.0000x reference)
#include <cuda_runtime.h>
#include <cuda_fp16.h>
#include <math.h>
#include <stdint.h>

#define HH 96
#define WW 160
#define HW (HH*WW)
#define NTOT2 (8*128*HW)     // words in a packed 256-channel fp16 tensor

// scratch (allocation-free rule: __device__ globals)
__device__ uint32_t g_fh [8*128*HW];    // features, packed fp16
__device__ uint32_t g_h1h[8*128*HW];    // conv1 out
__device__ uint32_t g_w1h[72*2*2048];
__device__ uint32_t g_w2h[72*2*2048];
__device__ uint32_t g_uwh[72*1*2048];
__device__ float    g_accd[8*HW];       // fused depth-head accumulator
__device__ float    g_accu[8*HW];       // fused uncertainty-head accumulator

__device__ __forceinline__ void mma_f16(float* d, const uint32_t* a, const uint32_t* b){
    asm volatile(
        "mma.sync.aligned.m16n8k16.row.col.f32.f16.f16.f32 "
        "{%0,%1,%2,%3}, {%4,%5,%6,%7}, {%8,%9}, {%0,%1,%2,%3};"
        : "+f"(d[0]), "+f"(d[1]), "+f"(d[2]), "+f"(d[3])
        : "r"(a[0]), "r"(a[1]), "r"(a[2]), "r"(a[3]), "r"(b[0]), "r"(b[1]));
}
__device__ __forceinline__ void cp16(uint32_t smem_dst, const void* gptr){
    asm volatile("cp.async.cg.shared.global [%0], [%1], 16;" :: "r"(smem_dst), "l"(gptr));
}
__device__ __forceinline__ void cp_commit(){ asm volatile("cp.async.commit_group;"); }

// stage layout (words): A = 2 frag blocks x 2304 = 4608 ; B = 32 x 264 = 8448
#define A_WORDS 4608
#define BROW    264
#define STG_W   13056
#define NSTAGE  3
#define SMEM_DYN (NSTAGE*STG_W*4)   // 156672 B/CTA -> 1 CTA/SM

// ---------------------------------------------------------------------------
// zero both head accumulators (graph-safe: plain kernel launch)
// ---------------------------------------------------------------------------
__global__ void zero2(float* a, float* b){
    int i = blockIdx.x*256 + threadIdx.x;
    if (i < 8*HW) { a[i] = 0.f; b[i] = 0.f; }
}

// ---------------------------------------------------------------------------
// features f32 planar -> packed half2 (ic-pair interleaved)
// ---------------------------------------------------------------------------
__global__ void f2h(const float* __restrict__ src, uint32_t* __restrict__ dst){
    int w = blockIdx.x*256 + threadIdx.x;
    if (w >= NTOT2) return;
    int p = w % HW; int r = w / HW; int ic2 = r & 127; int b = r >> 7;
    float lo = src[((size_t)(b*256 + 2*ic2    ))*HW + p];
    float hi = src[((size_t)(b*256 + 2*ic2 + 1))*HW + p];
    __half2 h = __floats2half2_rn(lo, hi);
    dst[w] = *(uint32_t*)&h;
}

// ---------------------------------------------------------------------------
// Weight transform: w[oc][ic][3][3] -> fp16 fragment-major (m16n8k16 A layout)
// ---------------------------------------------------------------------------
__global__ void wtrans16(const float* __restrict__ w, uint32_t* __restrict__ wt, int OC){
    int W = blockIdx.x*256 + threadIdx.x;
    int nT = OC >> 7;
    int total = 72*nT*2048;
    if (W >= total) return;
    int o    = W & 31;
    int bIdx = (W >> 5) & 63;
    int rest = W >> 11;
    int ocT  = rest % nT;
    int ci   = rest / nT;
    int icb = ci & 7, t = ci >> 3;
    int mh = o >> 4, mt = (o >> 2) & 3, wrd = o & 3;
    int ks = bIdx >> 5, lg = (bIdx >> 2) & 7, lt = bIdx & 3;
    int ic = icb*32 + ks*16 + 2*lt + (wrd >> 1)*8;
    int oc = ocT*128 + mh*64 + mt*16 + lg + (wrd & 1)*8;
    float lo = w[((size_t)oc*256 + ic    )*9 + t];
    float hi = w[((size_t)oc*256 + ic + 1)*9 + t];
    __half2 h = __floats2half2_rn(lo, hi);
    wt[W] = *(uint32_t*)&h;
}

// ---------------------------------------------------------------------------
// fp16 m16n8k16 implicit-GEMM conv3x3 (pad 1) + BN/bias + ReLU.
// CTA: M=128 oc x N=256 flat pixels; warp tile 64x64 (2M x 4N warps).
// K-chunks of 64 (4 per tap), 36 syncs. fuse=0: packed-fp16 stores.
// fuse=1: per-pixel head dot reduced via shfl + f32 atomicAdd.
// ---------------------------------------------------------------------------
__global__ __launch_bounds__(256, 1) void conv3x3_mma(
    const uint32_t* __restrict__ in, const uint32_t* __restrict__ wt,
    const float* __restrict__ bias, const float* __restrict__ gam,
    const float* __restrict__ bet, const float* __restrict__ mu,
    const float* __restrict__ var, uint16_t* __restrict__ out,
    const float* __restrict__ hw, float* __restrict__ acc,
    int OC, int useBN, int fuse)
{
    extern __shared__ uint32_t sdyn[];
    __shared__ float sc_s[128], sh_s[128], hw_s[128];

    const int tid = threadIdx.x;
    const int wid = tid >> 5, lane = tid & 31;
    const int b = blockIdx.z;
    const int px0 = blockIdx.x * 256;
    const int oc0 = blockIdx.y * 128;
    const int nT  = OC >> 7;
    const int ocT = oc0 >> 7;
    const int OC2 = OC >> 1;

    if (tid < 128) {
        int oc = oc0 + tid;
        if (useBN) {
            float s = gam[oc] * rsqrtf(var[oc] + 1e-5f);
            sc_s[tid] = s;
            sh_s[tid] = (bias[oc] - mu[oc]) * s + bet[oc];
        } else {
            sc_s[tid] = 1.f;
            sh_s[tid] = bias[oc];
        }
        if (fuse) hw_s[tid] = hw[oc];
    }

    const uint32_t sbase = (uint32_t)__cvta_generic_to_shared(sdyn);
    const int a_dw0 = (tid >> 2)*36 + ((tid >> 1) & 1)*16 + (tid & 1)*8;

    const int mh  = wid & 1;           // M half: rows mh*64 .. +63
    const int n0w = (wid >> 1) * 64;   // N quarter: 64 pixels
    const int lg  = lane >> 2;
    const int lt  = lane & 3;

    int xv[8], yv[8];
    #pragma unroll
    for (int nt = 0; nt < 8; nt++) {
        int p = px0 + n0w + nt*8 + lg;
        yv[nt] = p / WW;
        xv[nt] = p - yv[nt]*WW;
    }

    float d[4][8][4];
    #pragma unroll
    for (int mt = 0; mt < 4; mt++)
        #pragma unroll
        for (int nt = 0; nt < 8; nt++)
            #pragma unroll
            for (int q = 0; q < 4; q++) d[mt][nt][q] = 0.f;

    // stage issuer for K-chunk of 64 (tap t = s>>2, ic blocks icb0, icb0+1)
    auto issue = [&](int s){
        const int slot = s % NSTAGE;
        const int t = s >> 2, icb0 = (s & 3) << 1;
        const int khs = (t*11) >> 5;           // t/3
        // A: 4 cp16 (two fragment-major 32K blocks)
        uint32_t ad = sbase + (uint32_t)(slot*STG_W + a_dw0)*4;
        #pragma unroll
        for (int blk = 0; blk < 2; blk++) {
            const uint32_t* ap = wt +
                ((size_t)((t*8 + icb0 + blk)*nT + ocT))*2048 + tid*8;
            cp16(ad + (uint32_t)blk*2304*4,      ap);
            cp16(ad + (uint32_t)blk*2304*4 + 16, ap + 4);
        }
        // B: 32 half2-rows x 66 cp16 segs (2112), unshifted (kh in base)
        const int rbase = (b*128 + icb0*16)*HW + px0 - 4 + (khs-1)*WW;
        const uint32_t bd0 = sbase + (uint32_t)(slot*STG_W + A_WORDS)*4;
        for (int q = tid; q < 2112; q += 256) {
            int row = q / 66, seg = q - row*66;
            int o = rbase + row*HW + seg*4;
            o = min(max(o, 0), NTOT2 - 4);
            cp16(bd0 + (uint32_t)(row*BROW + seg*4)*4, in + o);
        }
        cp_commit();
    };

    issue(0); issue(1);

    uint32_t vm[8];
    int koff = 0;

    for (int c = 0; c < 36; c++) {
        if (c < 35) asm volatile("cp.async.wait_group 1;");
        else        asm volatile("cp.async.wait_group 0;");
        __syncthreads();

        if (c + 2 < 36) issue(c + 2);

        if ((c & 3) == 0) {           // new tap: masks + kw read offset
            const int tc = c >> 2;
            const int khc = (tc*11) >> 5, kwc = tc - khc*3;
            koff = kwc + 3;
            #pragma unroll
            for (int nt = 0; nt < 8; nt++) {
                bool v = ((unsigned)(yv[nt] + khc - 1) < HH) &&
                         ((unsigned)(xv[nt] + kwc - 1) < WW);
                vm[nt] = v ? 0xFFFFFFFFu : 0u;
            }
        }

        const int slot = c % NSTAGE;
        const uint32_t* sA = sdyn + slot*STG_W;
        const uint32_t* sB = sA + A_WORDS;

        #pragma unroll
        for (int ks = 0; ks < 4; ks++) {
            const int abase = (ks >> 1)*2304 +
                              (((ks & 1)*32) + lg*4 + lt)*36 + mh*16;
            uint4 a4[4];
            #pragma unroll
            for (int mt = 0; mt < 4; mt++)
                a4[mt] = *(const uint4*)(sA + abase + mt*4);

            uint32_t bf[8][2];
            const int kr0 = (ks*8 + lt)*BROW + koff;
            #pragma unroll
            for (int nt = 0; nt < 8; nt++) {
                int ncol = n0w + nt*8 + lg;
                bf[nt][0] = sB[kr0          + ncol] & vm[nt];
                bf[nt][1] = sB[kr0 + 4*BROW + ncol] & vm[nt];
            }
            #pragma unroll
            for (int mt = 0; mt < 4; mt++)
                #pragma unroll
                for (int nt = 0; nt < 8; nt++)
                    mma_f16(d[mt][nt], (const uint32_t*)&a4[mt], bf[nt]);
        }
    }
    __syncthreads();

    if (!fuse) {
        // epilogue: BN + ReLU + packed-fp16 stores
        #pragma unroll
        for (int mt = 0; mt < 4; mt++) {
            int r0 = mh*64 + mt*16 + lg;
            int oca = oc0 + r0, ocb = oca + 8;
            float sc0 = sc_s[r0],     sh0 = sh_s[r0];
            float sc1 = sc_s[r0 + 8], sh1 = sh_s[r0 + 8];
            size_t pa = ((size_t)(b*OC2 + (oca >> 1))*HW);
            size_t pb = ((size_t)(b*OC2 + (ocb >> 1))*HW);
            int la = oca & 1, lb = ocb & 1;
            #pragma unroll
            for (int nt = 0; nt < 8; nt++) {
                int p0 = px0 + n0w + nt*8 + 2*lt;
                float v0 = d[mt][nt][0] * sc0 + sh0;
                float v1 = d[mt][nt][1] * sc0 + sh0;
                float v2 = d[mt][nt][2] * sc1 + sh1;
                float v3 = d[mt][nt][3] * sc1 + sh1;
                v0 = v0 > 0.f ? v0 : 0.f;  v1 = v1 > 0.f ? v1 : 0.f;
                v2 = v2 > 0.f ? v2 : 0.f;  v3 = v3 > 0.f ? v3 : 0.f;
                out[((pa + p0    ) << 1) | la] = __half_as_ushort(__float2half_rn(v0));
                out[((pa + p0 + 1) << 1) | la] = __half_as_ushort(__float2half_rn(v1));
                out[((pb + p0    ) << 1) | lb] = __half_as_ushort(__float2half_rn(v2));
                out[((pb + p0 + 1) << 1) | lb] = __half_as_ushort(__float2half_rn(v3));
            }
        }
    } else {
        // fused head: per-pixel partial dot over this thread's 8 oc rows
        float hs0[8], hs1[8];
        #pragma unroll
        for (int nt = 0; nt < 8; nt++) { hs0[nt] = 0.f; hs1[nt] = 0.f; }
        #pragma unroll
        for (int mt = 0; mt < 4; mt++) {
            int r0 = mh*64 + mt*16 + lg;
            float sc0 = sc_s[r0],     sh0 = sh_s[r0];
            float sc1 = sc_s[r0 + 8], sh1 = sh_s[r0 + 8];
            float w0 = hw_s[r0], w1 = hw_s[r0 + 8];
            #pragma unroll
            for (int nt = 0; nt < 8; nt++) {
                float v0 = d[mt][nt][0] * sc0 + sh0;
                float v1 = d[mt][nt][1] * sc0 + sh0;
                float v2 = d[mt][nt][2] * sc1 + sh1;
                float v3 = d[mt][nt][3] * sc1 + sh1;
                v0 = v0 > 0.f ? v0 : 0.f;  v1 = v1 > 0.f ? v1 : 0.f;
                v2 = v2 > 0.f ? v2 : 0.f;  v3 = v3 > 0.f ? v3 : 0.f;
                hs0[nt] += v0 * w0 + v2 * w1;
                hs1[nt] += v1 * w0 + v3 * w1;
            }
        }
        // reduce over lg (lanes lt, lt+4, ..., lt+28)
        #pragma unroll
        for (int nt = 0; nt < 8; nt++) {
            #pragma unroll
            for (int off = 16; off >= 4; off >>= 1) {
                hs0[nt] += __shfl_down_sync(0xFFFFFFFFu, hs0[nt], off);
                hs1[nt] += __shfl_down_sync(0xFFFFFFFFu, hs1[nt], off);
            }
        }
        if (lg == 0) {
            float* ab = acc + (size_t)b * HW;
            #pragma unroll
            for (int nt = 0; nt < 8; nt++) {
                int p0 = px0 + n0w + nt*8 + 2*lt;
                atomicAdd(ab + p0,     hs0[nt]);
                atomicAdd(ab + p0 + 1, hs1[nt]);
            }
        }
    }
}

// ---------------------------------------------------------------------------
// head finish: mode 0 -> sigmoid->depth ; mode 1 -> softplus
// ---------------------------------------------------------------------------
__global__ __launch_bounds__(256) void finish(
    const float* __restrict__ acc, const float* __restrict__ bias,
    float* __restrict__ out, int mode)
{
    int idx = blockIdx.x * 256 + threadIdx.x;
    float v = acc[idx] + bias[0];
    float res;
    if (mode == 0) {
        float disp = 1.f / (1.f + expf(-v));
        res = 1.f / (0.01f + 9.99f * disp);
    } else {
        res = v > 20.f ? v : log1pf(expf(v));
    }
    out[idx] = res;
}

// ---------------------------------------------------------------------------
// Per-box lower median via exact 32-bit radix select (on f32 depth).
// ---------------------------------------------------------------------------
__global__ __launch_bounds__(256) void box_median(
    const float* __restrict__ depth, const int* __restrict__ bboxes,
    float* __restrict__ out)
{
    const int bi = blockIdx.x;
    const int b = bi >> 6;
    const int tid = threadIdx.x;
    const int* box = bboxes + (size_t)bi * 4;

    int x1 = max(box[0], 0), y1 = max(box[1], 0);
    int x2 = min(box[2], WW), y2 = min(box[3], HH);
    int wdt = x2 - x1, hgt = y2 - y1;
    if (wdt <= 0 || hgt <= 0) {
        if (tid == 0) out[bi] = 0.f;
        return;
    }
    const int k = wdt * hgt;
    int r = (k - 1) >> 1;

    __shared__ unsigned hist[256];
    const float* dimg = depth + (size_t)b * HW;
    unsigned prefix = 0;

    for (int pass = 0; pass < 4; ++pass) {
        int shift = 24 - 8*pass;
        hist[tid] = 0;
        __syncthreads();
        unsigned pmask = (pass == 0) ? 0u : (0xFFFFFFFFu << (shift + 8));
        for (int e = tid; e < k; e += 256) {
            int y = y1 + e / wdt, x = x1 + e % wdt;
            unsigned bits = __float_as_uint(dimg[y*WW + x]);
            if ((bits & pmask) == prefix)
                atomicAdd(&hist[(bits >> shift) & 0xFF], 1u);
        }
        __syncthreads();
        unsigned cum = 0; int bin = -1;
        for (int i = 0; i < 256; i++) {
            unsigned h = hist[i];
            if (bin < 0 && r < (int)(cum + h)) { bin = i; r -= (int)cum; }
            cum += h;
        }
        prefix |= ((unsigned)bin) << shift;
        __syncthreads();
    }
    if (tid == 0) out[bi] = __uint_as_float(prefix);
}

// ---------------------------------------------------------------------------
extern "C" void kernel_launch(void* const* d_in, const int* in_sizes, int n_in,
                              void* d_out, int out_size)
{
    const float* features = (const float*)d_in[0];
    const int*   bboxes   = (const int*)  d_in[1];
    const float* w1  = (const float*)d_in[2];
    const float* b1  = (const float*)d_in[3];
    const float* g1  = (const float*)d_in[4];
    const float* be1 = (const float*)d_in[5];
    const float* m1  = (const float*)d_in[6];
    const float* v1  = (const float*)d_in[7];
    const float* w2  = (const float*)d_in[8];
    const float* b2  = (const float*)d_in[9];
    const float* g2  = (const float*)d_in[10];
    const float* be2 = (const float*)d_in[11];
    const float* m2  = (const float*)d_in[12];
    const float* v2  = (const float*)d_in[13];
    const float* w3  = (const float*)d_in[14];
    const float* b3  = (const float*)d_in[15];
    const float* uw1 = (const float*)d_in[16];
    const float* ub1 = (const float*)d_in[17];
    const float* uw2 = (const float*)d_in[18];
    const float* ub2 = (const float*)d_in[19];

    float* out = (float*)d_out;

    uint32_t *fh, *h1h, *w1h, *w2h, *uwh;
    float *accd, *accu;
    cudaGetSymbolAddress((void**)&fh,   g_fh);
    cudaGetSymbolAddress((void**)&h1h,  g_h1h);
    cudaGetSymbolAddress((void**)&w1h,  g_w1h);
    cudaGetSymbolAddress((void**)&w2h,  g_w2h);
    cudaGetSymbolAddress((void**)&uwh,  g_uwh);
    cudaGetSymbolAddress((void**)&accd, g_accd);
    cudaGetSymbolAddress((void**)&accu, g_accu);

    cudaFuncSetAttribute(conv3x3_mma,
        cudaFuncAttributeMaxDynamicSharedMemorySize, SMEM_DYN);

    // zero head accumulators (kernel launch, graph-safe)
    zero2<<<480, 256>>>(accd, accu);

    // input + weight conversions
    f2h<<<(NTOT2 + 255)/256, 256>>>(features, fh);
    wtrans16<<<(72*2*2048 + 255)/256, 256>>>(w1,  w1h, 256);
    wtrans16<<<(72*2*2048 + 255)/256, 256>>>(w2,  w2h, 256);
    wtrans16<<<(72*1*2048 + 255)/256, 256>>>(uw1, uwh, 128);

    dim3 g256(60, 2, 8);   // 60 pixel tiles (256 px), 2 oc-tiles, 8 batch
    dim3 g128(60, 1, 8);

    // depth head
    conv3x3_mma<<<g256, 256, SMEM_DYN>>>(fh,  w1h, b1, g1, be1, m1, v1,
        (uint16_t*)h1h, (const float*)0, (float*)0, 256, 1, 0);
    conv3x3_mma<<<g256, 256, SMEM_DYN>>>(h1h, w2h, b2, g2, be2, m2, v2,
        (uint16_t*)0, w3, accd, 256, 1, 1);
    finish<<<480, 256>>>(accd, b3, out, 0);                          // depth

    // uncertainty head
    conv3x3_mma<<<g128, 256, SMEM_DYN>>>(fh, uwh, ub1,
        (const float*)0, (const float*)0, (const float*)0, (const float*)0,
        (uint16_t*)0, uw2, accu, 128, 0, 1);
    finish<<<480, 256>>>(accu, ub2, out + 122880, 1);                // uncertainty

    // per-box medians from depth
    box_median<<<512, 256>>>(out, bboxes, out + 245760);             // obj depths
}

// round 15
// speedup vs baseline: 1.1458x; 1.1458x over previous
#include <cuda_runtime.h>
#include <cuda_fp16.h>
#include <math.h>
#include <stdint.h>

#define HH 96
#define WW 160
#define HW (HH*WW)
#define NTOT2 (8*128*HW)     // words in a packed 256-channel fp16 tensor

// scratch (allocation-free rule: __device__ globals)
__device__ uint32_t g_fh [8*128*HW];    // features, packed fp16
__device__ uint32_t g_h1h[8*128*HW];    // conv1 out
__device__ uint32_t g_w1h[72*2*2048];
__device__ uint32_t g_w2h[72*2*2048];
__device__ uint32_t g_uwh[72*1*2048];
__device__ float    g_accd[8*HW];       // fused depth-head accumulator
__device__ float    g_accu[8*HW];       // fused uncertainty-head accumulator

__device__ __forceinline__ void mma_f16(float* d, const uint32_t* a, const uint32_t* b){
    asm volatile(
        "mma.sync.aligned.m16n8k16.row.col.f32.f16.f16.f32 "
        "{%0,%1,%2,%3}, {%4,%5,%6,%7}, {%8,%9}, {%0,%1,%2,%3};"
        : "+f"(d[0]), "+f"(d[1]), "+f"(d[2]), "+f"(d[3])
        : "r"(a[0]), "r"(a[1]), "r"(a[2]), "r"(a[3]), "r"(b[0]), "r"(b[1]));
}
__device__ __forceinline__ void cp16(uint32_t smem_dst, const void* gptr){
    asm volatile("cp.async.cg.shared.global [%0], [%1], 16;" :: "r"(smem_dst), "l"(gptr));
}
__device__ __forceinline__ void cp_commit(){ asm volatile("cp.async.commit_group;"); }

// stage layout (words): A = 2 frag blocks x 2304 = 4608 ; B = 32 x 136 = 4352
#define A_WORDS 4608
#define STG_W   8960
#define NSTAGE  3
#define SMEM_DYN (NSTAGE*STG_W*4)   // 107520 B/CTA -> 2 CTAs/SM

// ---------------------------------------------------------------------------
__global__ void zero2(float* a, float* b){
    int i = blockIdx.x*256 + threadIdx.x;
    if (i < 8*HW) { a[i] = 0.f; b[i] = 0.f; }
}

// features f32 planar -> packed half2 (ic-pair interleaved)
__global__ void f2h(const float* __restrict__ src, uint32_t* __restrict__ dst){
    int w = blockIdx.x*256 + threadIdx.x;
    if (w >= NTOT2) return;
    int p = w % HW; int r = w / HW; int ic2 = r & 127; int b = r >> 7;
    float lo = src[((size_t)(b*256 + 2*ic2    ))*HW + p];
    float hi = src[((size_t)(b*256 + 2*ic2 + 1))*HW + p];
    __half2 h = __floats2half2_rn(lo, hi);
    dst[w] = *(uint32_t*)&h;
}

// Weight transform: w[oc][ic][3][3] -> fp16 fragment-major (m16n8k16 A layout)
__global__ void wtrans16(const float* __restrict__ w, uint32_t* __restrict__ wt, int OC){
    int W = blockIdx.x*256 + threadIdx.x;
    int nT = OC >> 7;
    int total = 72*nT*2048;
    if (W >= total) return;
    int o    = W & 31;
    int bIdx = (W >> 5) & 63;
    int rest = W >> 11;
    int ocT  = rest % nT;
    int ci   = rest / nT;
    int icb = ci & 7, t = ci >> 3;
    int mh = o >> 4, mt = (o >> 2) & 3, wrd = o & 3;
    int ks = bIdx >> 5, lg = (bIdx >> 2) & 7, lt = bIdx & 3;
    int ic = icb*32 + ks*16 + 2*lt + (wrd >> 1)*8;
    int oc = ocT*128 + mh*64 + mt*16 + lg + (wrd & 1)*8;
    float lo = w[((size_t)oc*256 + ic    )*9 + t];
    float hi = w[((size_t)oc*256 + ic + 1)*9 + t];
    __half2 h = __floats2half2_rn(lo, hi);
    wt[W] = *(uint32_t*)&h;
}

// ---------------------------------------------------------------------------
// shared conv body: fp16 m16n8k16 implicit-GEMM conv3x3 (pad 1).
// CTA: M=128 oc x N=128 px, warp tile 64x32; K-chunks of 64 (36 syncs).
// ---------------------------------------------------------------------------
__device__ __forceinline__ void conv_body(
    uint32_t* sdyn, float* sc_s, float* sh_s, float* hw_s,
    const uint32_t* __restrict__ in, const uint32_t* __restrict__ wt,
    int nT, int ocT,
    const float* __restrict__ bias, const float* __restrict__ gam,
    const float* __restrict__ bet, const float* __restrict__ mu,
    const float* __restrict__ var, uint16_t* __restrict__ out, int OC2,
    const float* __restrict__ hw, float* __restrict__ acc,
    int useBN, int fuse)
{
    const int tid = threadIdx.x;
    const int wid = tid >> 5, lane = tid & 31;
    const int b = blockIdx.z;
    const int px0 = blockIdx.x * 128;
    const int oc0 = ocT * 128;

    if (tid < 128) {
        int oc = oc0 + tid;
        if (useBN) {
            float s = gam[oc] * rsqrtf(var[oc] + 1e-5f);
            sc_s[tid] = s;
            sh_s[tid] = (bias[oc] - mu[oc]) * s + bet[oc];
        } else {
            sc_s[tid] = 1.f;
            sh_s[tid] = bias[oc];
        }
        if (fuse) hw_s[tid] = hw[oc];
    }

    const uint32_t sbase = (uint32_t)__cvta_generic_to_shared(sdyn);
    const int a_dw0 = (tid >> 2)*36 + ((tid >> 1) & 1)*16 + (tid & 1)*8;

    // precomputed B staging geometry (loop-invariant): 1088 cp16 = 32 rows x 34
    uint32_t bq_dst[5]; int bq_src[5]; bool bq_ok[5];
    #pragma unroll
    for (int i = 0; i < 5; i++) {
        int q = tid + i*256;
        bq_ok[i] = q < 1088;
        int row = q / 34, seg = q - row*34;
        bq_dst[i] = (uint32_t)(row*136 + seg*4)*4;
        bq_src[i] = row*HW + seg*4;
    }

    const int mh  = wid & 1;
    const int n0w = (wid >> 1) * 32;
    const int lg  = lane >> 2;
    const int lt  = lane & 3;

    int xv[4], yv[4];
    #pragma unroll
    for (int nt = 0; nt < 4; nt++) {
        int p = px0 + n0w + nt*8 + lg;
        yv[nt] = p / WW;
        xv[nt] = p - yv[nt]*WW;
    }

    float d[4][4][4];
    #pragma unroll
    for (int mt = 0; mt < 4; mt++)
        #pragma unroll
        for (int nt = 0; nt < 4; nt++)
            #pragma unroll
            for (int q = 0; q < 4; q++) d[mt][nt][q] = 0.f;

    auto issue = [&](int s){
        const int slot = s % NSTAGE;
        const int t = s >> 2, icb0 = (s & 3) << 1;
        const int khs = (t*11) >> 5;           // t/3
        uint32_t ad = sbase + (uint32_t)(slot*STG_W + a_dw0)*4;
        #pragma unroll
        for (int blk = 0; blk < 2; blk++) {
            const uint32_t* ap = wt +
                ((size_t)((t*8 + icb0 + blk)*nT + ocT))*2048 + tid*8;
            cp16(ad + (uint32_t)blk*2304*4,      ap);
            cp16(ad + (uint32_t)blk*2304*4 + 16, ap + 4);
        }
        const int rbase = (b*128 + icb0*16)*HW + px0 - 4 + (khs-1)*WW;
        const uint32_t bd0 = sbase + (uint32_t)(slot*STG_W + A_WORDS)*4;
        #pragma unroll
        for (int i = 0; i < 5; i++) {
            if (bq_ok[i]) {
                int o = rbase + bq_src[i];
                o = min(max(o, 0), NTOT2 - 4);
                cp16(bd0 + bq_dst[i], in + o);
            }
        }
        cp_commit();
    };

    issue(0); issue(1);

    uint32_t vm[4];
    int koff = 0;

    for (int c = 0; c < 36; c++) {
        if (c < 35) asm volatile("cp.async.wait_group 1;");
        else        asm volatile("cp.async.wait_group 0;");
        __syncthreads();

        if (c + 2 < 36) issue(c + 2);

        if ((c & 3) == 0) {
            const int tc = c >> 2;
            const int khc = (tc*11) >> 5, kwc = tc - khc*3;
            koff = kwc + 3;
            #pragma unroll
            for (int nt = 0; nt < 4; nt++) {
                bool v = ((unsigned)(yv[nt] + khc - 1) < HH) &&
                         ((unsigned)(xv[nt] + kwc - 1) < WW);
                vm[nt] = v ? 0xFFFFFFFFu : 0u;
            }
        }

        const int slot = c % NSTAGE;
        const uint32_t* sA = sdyn + slot*STG_W;
        const uint32_t* sB = sA + A_WORDS;

        #pragma unroll
        for (int ks = 0; ks < 4; ks++) {
            const int abase = (ks >> 1)*2304 +
                              (((ks & 1)*32) + lg*4 + lt)*36 + mh*16;
            uint4 a4[4];
            #pragma unroll
            for (int mt = 0; mt < 4; mt++)
                a4[mt] = *(const uint4*)(sA + abase + mt*4);

            uint32_t bf[4][2];
            const int kr0 = (ks*8 + lt)*136 + koff;
            #pragma unroll
            for (int nt = 0; nt < 4; nt++) {
                int ncol = n0w + nt*8 + lg;
                bf[nt][0] = sB[kr0         + ncol] & vm[nt];
                bf[nt][1] = sB[kr0 + 4*136 + ncol] & vm[nt];
            }
            #pragma unroll
            for (int mt = 0; mt < 4; mt++)
                #pragma unroll
                for (int nt = 0; nt < 4; nt++)
                    mma_f16(d[mt][nt], (const uint32_t*)&a4[mt], bf[nt]);
        }
    }
    __syncthreads();

    if (!fuse) {
        #pragma unroll
        for (int mt = 0; mt < 4; mt++) {
            int r0 = mh*64 + mt*16 + lg;
            int oca = oc0 + r0, ocb = oca + 8;
            float sc0 = sc_s[r0],     sh0 = sh_s[r0];
            float sc1 = sc_s[r0 + 8], sh1 = sh_s[r0 + 8];
            size_t pa = ((size_t)(b*OC2 + (oca >> 1))*HW);
            size_t pb = ((size_t)(b*OC2 + (ocb >> 1))*HW);
            int la = oca & 1, lb = ocb & 1;
            #pragma unroll
            for (int nt = 0; nt < 4; nt++) {
                int p0 = px0 + n0w + nt*8 + 2*lt;
                float v0 = d[mt][nt][0] * sc0 + sh0;
                float v1 = d[mt][nt][1] * sc0 + sh0;
                float v2 = d[mt][nt][2] * sc1 + sh1;
                float v3 = d[mt][nt][3] * sc1 + sh1;
                v0 = v0 > 0.f ? v0 : 0.f;  v1 = v1 > 0.f ? v1 : 0.f;
                v2 = v2 > 0.f ? v2 : 0.f;  v3 = v3 > 0.f ? v3 : 0.f;
                out[((pa + p0    ) << 1) | la] = __half_as_ushort(__float2half_rn(v0));
                out[((pa + p0 + 1) << 1) | la] = __half_as_ushort(__float2half_rn(v1));
                out[((pb + p0    ) << 1) | lb] = __half_as_ushort(__float2half_rn(v2));
                out[((pb + p0 + 1) << 1) | lb] = __half_as_ushort(__float2half_rn(v3));
            }
        }
    } else {
        float hs0[4], hs1[4];
        #pragma unroll
        for (int nt = 0; nt < 4; nt++) { hs0[nt] = 0.f; hs1[nt] = 0.f; }
        #pragma unroll
        for (int mt = 0; mt < 4; mt++) {
            int r0 = mh*64 + mt*16 + lg;
            float sc0 = sc_s[r0],     sh0 = sh_s[r0];
            float sc1 = sc_s[r0 + 8], sh1 = sh_s[r0 + 8];
            float w0 = hw_s[r0], w1 = hw_s[r0 + 8];
            #pragma unroll
            for (int nt = 0; nt < 4; nt++) {
                float v0 = d[mt][nt][0] * sc0 + sh0;
                float v1 = d[mt][nt][1] * sc0 + sh0;
                float v2 = d[mt][nt][2] * sc1 + sh1;
                float v3 = d[mt][nt][3] * sc1 + sh1;
                v0 = v0 > 0.f ? v0 : 0.f;  v1 = v1 > 0.f ? v1 : 0.f;
                v2 = v2 > 0.f ? v2 : 0.f;  v3 = v3 > 0.f ? v3 : 0.f;
                hs0[nt] += v0 * w0 + v2 * w1;
                hs1[nt] += v1 * w0 + v3 * w1;
            }
        }
        #pragma unroll
        for (int nt = 0; nt < 4; nt++) {
            #pragma unroll
            for (int off = 16; off >= 4; off >>= 1) {
                hs0[nt] += __shfl_down_sync(0xFFFFFFFFu, hs0[nt], off);
                hs1[nt] += __shfl_down_sync(0xFFFFFFFFu, hs1[nt], off);
            }
        }
        if (lg == 0) {
            float* ab = acc + (size_t)b * HW;
            #pragma unroll
            for (int nt = 0; nt < 4; nt++) {
                int p0 = px0 + n0w + nt*8 + 2*lt;
                atomicAdd(ab + p0,     hs0[nt]);
                atomicAdd(ab + p0 + 1, hs1[nt]);
            }
        }
    }
}

// ---------------------------------------------------------------------------
// first layer: grid.y = 3. y in {0,1}: conv1 (BN+ReLU, store h1h).
// y == 2: uncertainty conv (bias+ReLU) with fused softplus-head dot.
// ---------------------------------------------------------------------------
__global__ __launch_bounds__(256, 2) void convFirst(
    const uint32_t* __restrict__ in, const uint32_t* __restrict__ wt1,
    const uint32_t* __restrict__ uwt,
    const float* __restrict__ b1, const float* __restrict__ g1,
    const float* __restrict__ be1, const float* __restrict__ m1,
    const float* __restrict__ v1, const float* __restrict__ ub1,
    const float* __restrict__ uw2,
    uint16_t* __restrict__ out, float* __restrict__ accu)
{
    extern __shared__ uint32_t sdyn[];
    __shared__ float sc_s[128], sh_s[128], hw_s[128];
    int y = blockIdx.y;
    if (y < 2) {
        conv_body(sdyn, sc_s, sh_s, hw_s, in, wt1, 2, y,
                  b1, g1, be1, m1, v1, out, 128,
                  (const float*)0, (float*)0, 1, 0);
    } else {
        conv_body(sdyn, sc_s, sh_s, hw_s, in, uwt, 1, 0,
                  ub1, (const float*)0, (const float*)0, (const float*)0,
                  (const float*)0, (uint16_t*)0, 64,
                  uw2, accu, 0, 1);
    }
}

// ---------------------------------------------------------------------------
// second layer: conv2 with BN+ReLU and fused depth-head dot. grid.y = 2.
// ---------------------------------------------------------------------------
__global__ __launch_bounds__(256, 2) void convFused(
    const uint32_t* __restrict__ in, const uint32_t* __restrict__ wt,
    const float* __restrict__ bias, const float* __restrict__ gam,
    const float* __restrict__ bet, const float* __restrict__ mu,
    const float* __restrict__ var, const float* __restrict__ hw,
    float* __restrict__ acc)
{
    extern __shared__ uint32_t sdyn[];
    __shared__ float sc_s[128], sh_s[128], hw_s[128];
    conv_body(sdyn, sc_s, sh_s, hw_s, in, wt, 2, blockIdx.y,
              bias, gam, bet, mu, var, (uint16_t*)0, 128,
              hw, acc, 1, 1);
}

// ---------------------------------------------------------------------------
// head finish: mode 0 -> sigmoid->depth ; mode 1 -> softplus
// ---------------------------------------------------------------------------
__global__ __launch_bounds__(256) void finish(
    const float* __restrict__ acc, const float* __restrict__ bias,
    float* __restrict__ out, int mode)
{
    int idx = blockIdx.x * 256 + threadIdx.x;
    float v = acc[idx] + bias[0];
    float res;
    if (mode == 0) {
        float disp = 1.f / (1.f + expf(-v));
        res = 1.f / (0.01f + 9.99f * disp);
    } else {
        res = v > 20.f ? v : log1pf(expf(v));
    }
    out[idx] = res;
}

// ---------------------------------------------------------------------------
// Per-box lower median via exact 32-bit radix select (on f32 depth).
// ---------------------------------------------------------------------------
__global__ __launch_bounds__(256) void box_median(
    const float* __restrict__ depth, const int* __restrict__ bboxes,
    float* __restrict__ out)
{
    const int bi = blockIdx.x;
    const int b = bi >> 6;
    const int tid = threadIdx.x;
    const int* box = bboxes + (size_t)bi * 4;

    int x1 = max(box[0], 0), y1 = max(box[1], 0);
    int x2 = min(box[2], WW), y2 = min(box[3], HH);
    int wdt = x2 - x1, hgt = y2 - y1;
    if (wdt <= 0 || hgt <= 0) {
        if (tid == 0) out[bi] = 0.f;
        return;
    }
    const int k = wdt * hgt;
    int r = (k - 1) >> 1;

    __shared__ unsigned hist[256];
    const float* dimg = depth + (size_t)b * HW;
    unsigned prefix = 0;

    for (int pass = 0; pass < 4; ++pass) {
        int shift = 24 - 8*pass;
        hist[tid] = 0;
        __syncthreads();
        unsigned pmask = (pass == 0) ? 0u : (0xFFFFFFFFu << (shift + 8));
        for (int e = tid; e < k; e += 256) {
            int y = y1 + e / wdt, x = x1 + e % wdt;
            unsigned bits = __float_as_uint(dimg[y*WW + x]);
            if ((bits & pmask) == prefix)
                atomicAdd(&hist[(bits >> shift) & 0xFF], 1u);
        }
        __syncthreads();
        unsigned cum = 0; int bin = -1;
        for (int i = 0; i < 256; i++) {
            unsigned h = hist[i];
            if (bin < 0 && r < (int)(cum + h)) { bin = i; r -= (int)cum; }
            cum += h;
        }
        prefix |= ((unsigned)bin) << shift;
        __syncthreads();
    }
    if (tid == 0) out[bi] = __uint_as_float(prefix);
}

// ---------------------------------------------------------------------------
extern "C" void kernel_launch(void* const* d_in, const int* in_sizes, int n_in,
                              void* d_out, int out_size)
{
    const float* features = (const float*)d_in[0];
    const int*   bboxes   = (const int*)  d_in[1];
    const float* w1  = (const float*)d_in[2];
    const float* b1  = (const float*)d_in[3];
    const float* g1  = (const float*)d_in[4];
    const float* be1 = (const float*)d_in[5];
    const float* m1  = (const float*)d_in[6];
    const float* v1  = (const float*)d_in[7];
    const float* w2  = (const float*)d_in[8];
    const float* b2  = (const float*)d_in[9];
    const float* g2  = (const float*)d_in[10];
    const float* be2 = (const float*)d_in[11];
    const float* m2  = (const float*)d_in[12];
    const float* v2  = (const float*)d_in[13];
    const float* w3  = (const float*)d_in[14];
    const float* b3  = (const float*)d_in[15];
    const float* uw1 = (const float*)d_in[16];
    const float* ub1 = (const float*)d_in[17];
    const float* uw2 = (const float*)d_in[18];
    const float* ub2 = (const float*)d_in[19];

    float* out = (float*)d_out;

    uint32_t *fh, *h1h, *w1h, *w2h, *uwh;
    float *accd, *accu;
    cudaGetSymbolAddress((void**)&fh,   g_fh);
    cudaGetSymbolAddress((void**)&h1h,  g_h1h);
    cudaGetSymbolAddress((void**)&w1h,  g_w1h);
    cudaGetSymbolAddress((void**)&w2h,  g_w2h);
    cudaGetSymbolAddress((void**)&uwh,  g_uwh);
    cudaGetSymbolAddress((void**)&accd, g_accd);
    cudaGetSymbolAddress((void**)&accu, g_accu);

    cudaFuncSetAttribute(convFirst,
        cudaFuncAttributeMaxDynamicSharedMemorySize, SMEM_DYN);
    cudaFuncSetAttribute(convFused,
        cudaFuncAttributeMaxDynamicSharedMemorySize, SMEM_DYN);

    // zero head accumulators (kernel launch, graph-safe)
    zero2<<<480, 256>>>(accd, accu);

    // input + weight conversions
    f2h<<<(NTOT2 + 255)/256, 256>>>(features, fh);
    wtrans16<<<(72*2*2048 + 255)/256, 256>>>(w1,  w1h, 256);
    wtrans16<<<(72*2*2048 + 255)/256, 256>>>(w2,  w2h, 256);
    wtrans16<<<(72*1*2048 + 255)/256, 256>>>(uw1, uwh, 128);

    // layer 1: conv1 (2 oc tiles) + fused uncertainty head (1 tile)
    dim3 gA(120, 3, 8);
    convFirst<<<gA, 256, SMEM_DYN>>>(fh, w1h, uwh, b1, g1, be1, m1, v1,
                                     ub1, uw2, (uint16_t*)h1h, accu);

    // layer 2: conv2 + fused depth head
    dim3 gB(120, 2, 8);
    convFused<<<gB, 256, SMEM_DYN>>>(h1h, w2h, b2, g2, be2, m2, v2, w3, accd);

    finish<<<480, 256>>>(accd, b3, out, 0);                          // depth
    finish<<<480, 256>>>(accu, ub2, out + 122880, 1);                // uncertainty

    // per-box medians from depth
    box_median<<<512, 256>>>(out, bboxes, out + 245760);             // obj depths
}